// round 12
// baseline (speedup 1.0000x reference)
#include <cuda_runtime.h>
#include <cuda_fp16.h>
#include <math.h>

#define NN 50000
#define EE 1600000
#define GG 64
#define NODE_IN 32
#define HID 64
#define EDGE_IN 16
#define NLAYER 3

// ---------------- device scratch (static globals; no runtime alloc) ----------------
__device__ float d_h[NN * HID];
__device__ float d_qn[NN * HID];
__device__ __align__(16) __half d_kvh[NN * 128];   // interleaved K|V fp16: lane hl -> [K4|V4]
__device__ float d_sn[NN * HID];
__device__ float d_qwn[NN * HID];   // per-node q.We projection (4 heads x 16 r, packed)
__device__ int   d_deg[NN];
__device__ int   d_offs[NN + 1];
__device__ int   d_cursor[NN];
__device__ int   d_bsum[64];
__device__ int   d_ssrc[EE];        // src sorted by dst (4B loads in attn loop)
__device__ __align__(16) __half d_seah[(size_t)EE * EDGE_IN];  // fp16 permuted edge_attr
__device__ float d_M[NLAYER * HID * HID];   // fused Wq x We matrices (all layers)
__device__ float d_bqw[NLAYER * HID];

__device__ __forceinline__ float ex2(float x) {
    float r;
    asm("ex2.approx.f32 %0, %1;" : "=f"(r) : "f"(x));
    return r;
}
__device__ __forceinline__ unsigned tf32of(float x) {
    unsigned r;
    asm("cvt.rna.tf32.f32 %0, %1;" : "=r"(r) : "f"(x));
    return r;
}

// ---------------- preprocessing: counting sort of edges by dst ----------------
__global__ void zero_deg_kernel() {
    int i = blockIdx.x * blockDim.x + threadIdx.x;
    if (i < NN) d_deg[i] = 0;
}

__global__ void hist_kernel(const int* __restrict__ ei) {
    int e = blockIdx.x * blockDim.x + threadIdx.x;
    if (e < EE) atomicAdd(&d_deg[ei[EE + e]], 1);
}

__global__ void scan1_kernel() {
    __shared__ int s[1024];
    int t = threadIdx.x;
    int i = blockIdx.x * 1024 + t;
    int v = (i < NN) ? d_deg[i] : 0;
    s[t] = v;
    __syncthreads();
    for (int o = 1; o < 1024; o <<= 1) {
        int x = (t >= o) ? s[t - o] : 0;
        __syncthreads();
        s[t] += x;
        __syncthreads();
    }
    if (i < NN) d_offs[i] = s[t] - v;
    if (t == 1023) d_bsum[blockIdx.x] = s[t];
}

// scan3 folds the cross-block prefix: each block loads the <=64 block sums into
// smem and sums below its own block id.
__global__ void scan3_kernel(int nb) {
    __shared__ int pref[64];
    int t = threadIdx.x;
    if (t < nb) pref[t] = d_bsum[t];
    __syncthreads();
    int i = blockIdx.x * 256 + t;
    if (i < NN) {
        int b = i >> 10;
        int add = 0;
        for (int j = 0; j < b; j++) add += pref[j];
        int v = d_offs[i] + add;
        d_offs[i] = v;
        d_cursor[i] = v;
    }
    if (i == 0) {
        int tot = 0;
        for (int j = 0; j < nb; j++) tot += pref[j];
        d_offs[NN] = tot;   // == EE
    }
}

// scatter now also writes the fp16 permuted edge_attr: ea[e] read is coalesced
// (thread id == edge id); the 32B half-row is written to the sorted slot.
__global__ void scatter_kernel(const int* __restrict__ ei, const float* __restrict__ ea) {
    int e = blockIdx.x * blockDim.x + threadIdx.x;
    if (e < EE) {
        int dstv = ei[EE + e];
        int pos = atomicAdd(&d_cursor[dstv], 1);
        d_ssrc[pos] = ei[e];
        const float4* src = reinterpret_cast<const float4*>(ea) + (size_t)e * 4;
        float4 v0 = src[0], v1 = src[1], v2 = src[2], v3 = src[3];
        uint4 pk0, pk1;
        *reinterpret_cast<__half2*>(&pk0.x) = __floats2half2_rn(v0.x, v0.y);
        *reinterpret_cast<__half2*>(&pk0.y) = __floats2half2_rn(v0.z, v0.w);
        *reinterpret_cast<__half2*>(&pk0.z) = __floats2half2_rn(v1.x, v1.y);
        *reinterpret_cast<__half2*>(&pk0.w) = __floats2half2_rn(v1.z, v1.w);
        *reinterpret_cast<__half2*>(&pk1.x) = __floats2half2_rn(v2.x, v2.y);
        *reinterpret_cast<__half2*>(&pk1.y) = __floats2half2_rn(v2.z, v2.w);
        *reinterpret_cast<__half2*>(&pk1.z) = __floats2half2_rn(v3.x, v3.y);
        *reinterpret_cast<__half2*>(&pk1.w) = __floats2half2_rn(v3.z, v3.w);
        uint4* dst = reinterpret_cast<uint4*>(d_seah + (size_t)pos * 16);
        dst[0] = pk0;
        dst[1] = pk1;
    }
}

// ---------------- input embedding: h = relu(x @ Wn + bn) ----------------
__global__ __launch_bounds__(256) void node_in_kernel(const float* __restrict__ x,
                                                      const float* __restrict__ Wn,
                                                      const float* __restrict__ bn) {
    __shared__ float Wns[NODE_IN * HID];
    __shared__ float bns[HID];
    __shared__ float xs[4][NODE_IN];
    int t = threadIdx.x;
    for (int u = t; u < NODE_IN * HID; u += 256) Wns[u] = Wn[u];
    if (t < HID) bns[t] = bn[t];
    int j = t & 63, y = t >> 6;
    int node = blockIdx.x * 4 + y;
    if (j < NODE_IN && node < NN) xs[y][j] = x[node * NODE_IN + j];
    __syncthreads();
    if (node < NN) {
        float a = bns[j];
        #pragma unroll
        for (int k = 0; k < NODE_IN; k++) a += xs[y][k] * Wns[k * HID + j];
        d_h[(size_t)node * HID + j] = fmaxf(a, 0.f);
    }
}

// ---------------- all layers: M = per-head (Wq x We), bqw = per-head (bq x We) ----
__global__ void prep_M_kernel(const float* __restrict__ Wq, const float* __restrict__ bq,
                              const float* __restrict__ We) {
    int layer = blockIdx.y;
    int idx = blockIdx.x * 256 + threadIdx.x;
    const float* Wql = Wq + layer * HID * HID;
    const float* Wel = We + layer * EDGE_IN * HID;
    if (idx < HID * HID) {
        int krow = idx >> 6, col = idx & 63;
        int h = col >> 4, r = col & 15;
        float s = 0.f;
        #pragma unroll
        for (int c = 0; c < 16; c++)
            s += Wql[krow * HID + h * 16 + c] * Wel[r * HID + h * 16 + c];
        d_M[layer * HID * HID + idx] = s;
    }
    if (idx < HID) {
        int h = idx >> 4, r = idx & 15;
        const float* bql = bq + layer * HID;
        float s = 0.f;
        #pragma unroll
        for (int c = 0; c < 16; c++)
            s += bql[h * 16 + c] * Wel[r * HID + h * 16 + c];
        d_bqw[layer * HID + idx] = s;
    }
}

// ---------------- fused Q/K/V/Skip/QW node GEMM — tf32 tensor cores --------------
#define HS_STRIDE 68
#define WS_STRIDE 328
__global__ __launch_bounds__(256) void qkvs_kernel(
    const float* __restrict__ Wq, const float* __restrict__ bq,
    const float* __restrict__ Wk, const float* __restrict__ bk,
    const float* __restrict__ Wv, const float* __restrict__ bv,
    const float* __restrict__ Ws, const float* __restrict__ bs, int layer) {
    extern __shared__ float sm[];
    float* hs  = sm;                               // 64 x 68
    float* ws  = sm + 64 * HS_STRIDE;              // 64 x 328 (320 used)
    float* bss = sm + 64 * HS_STRIDE + 64 * WS_STRIDE;   // 320 bias values
    const float* Wm[5] = {Wq + layer * HID * HID, Wk + layer * HID * HID,
                          Wv + layer * HID * HID, Ws + layer * HID * HID,
                          d_M + layer * HID * HID};
    const float* bm[5] = {bq + layer * HID, bk + layer * HID, bv + layer * HID,
                          bs + layer * HID, d_bqw + layer * HID};
    int t = threadIdx.x;
    int node0 = blockIdx.x * 64;

    #pragma unroll
    for (int u = 0; u < 20; u++) {
        int mat = u >> 2;
        int e0 = ((u & 3) * 256 + t) * 4;
        int k = e0 >> 6, jj = e0 & 63;
        float4 w4 = *reinterpret_cast<const float4*>(Wm[mat] + k * HID + jj);
        *reinterpret_cast<float4*>(ws + k * WS_STRIDE + mat * 64 + jj) = w4;
    }
    #pragma unroll
    for (int u = 0; u < 4; u++) {
        int e0 = (u * 256 + t) * 4;
        int row = e0 >> 6, k = e0 & 63;
        int node = node0 + row;
        float4 h4 = make_float4(0.f, 0.f, 0.f, 0.f);
        if (node < NN) h4 = *reinterpret_cast<const float4*>(d_h + (size_t)node * HID + k);
        *reinterpret_cast<float4*>(hs + row * HS_STRIDE + k) = h4;
    }
    for (int u = t; u < 320; u += 256) bss[u] = bm[u >> 6][u & 63];
    __syncthreads();

    int warp = t >> 5;
    int lane = t & 31;
    int rb = warp >> 1;
    int cb = warp & 1;
    int gid = lane >> 2;
    int tg  = lane & 3;

    float c[20][4];
    #pragma unroll
    for (int nt = 0; nt < 20; nt++) {
        c[nt][0] = 0.f; c[nt][1] = 0.f; c[nt][2] = 0.f; c[nt][3] = 0.f;
    }

    #pragma unroll
    for (int ks = 0; ks < 8; ks++) {
        int k0 = ks * 8;
        const float* hb = hs + (rb * 16) * HS_STRIDE + k0;
        unsigned a0 = tf32of(hb[gid * HS_STRIDE + tg]);
        unsigned a1 = tf32of(hb[(gid + 8) * HS_STRIDE + tg]);
        unsigned a2 = tf32of(hb[gid * HS_STRIDE + tg + 4]);
        unsigned a3 = tf32of(hb[(gid + 8) * HS_STRIDE + tg + 4]);
        #pragma unroll
        for (int nt = 0; nt < 20; nt++) {
            int coln = cb * 160 + nt * 8 + gid;
            unsigned b0 = tf32of(ws[(k0 + tg) * WS_STRIDE + coln]);
            unsigned b1 = tf32of(ws[(k0 + 4 + tg) * WS_STRIDE + coln]);
            asm volatile(
                "mma.sync.aligned.m16n8k8.row.col.f32.tf32.tf32.f32 "
                "{%0,%1,%2,%3}, {%4,%5,%6,%7}, {%8,%9}, {%0,%1,%2,%3};"
                : "+f"(c[nt][0]), "+f"(c[nt][1]), "+f"(c[nt][2]), "+f"(c[nt][3])
                : "r"(a0), "r"(a1), "r"(a2), "r"(a3), "r"(b0), "r"(b1));
        }
    }

    int r0 = node0 + rb * 16 + gid;
    int r1 = r0 + 8;
    #pragma unroll
    for (int nt = 0; nt < 20; nt++) {
        int col = cb * 160 + nt * 8 + tg * 2;
        int mat = col >> 6, jj = col & 63;
        float b0 = bss[col], b1 = bss[col + 1];
        float v00 = c[nt][0] + b0, v01 = c[nt][1] + b1;   // row r0
        float v10 = c[nt][2] + b0, v11 = c[nt][3] + b1;   // row r1
        if (mat == 0) {
            if (r0 < NN) *reinterpret_cast<float2*>(d_qn + (size_t)r0 * HID + jj) = make_float2(v00, v01);
            if (r1 < NN) *reinterpret_cast<float2*>(d_qn + (size_t)r1 * HID + jj) = make_float2(v10, v11);
        } else if (mat == 1) {
            int koff = (jj >> 2) * 8 + (jj & 3);
            if (r0 < NN) *reinterpret_cast<__half2*>(d_kvh + (size_t)r0 * 128 + koff) = __floats2half2_rn(v00, v01);
            if (r1 < NN) *reinterpret_cast<__half2*>(d_kvh + (size_t)r1 * 128 + koff) = __floats2half2_rn(v10, v11);
        } else if (mat == 2) {
            int voff = (jj >> 2) * 8 + 4 + (jj & 3);
            if (r0 < NN) *reinterpret_cast<__half2*>(d_kvh + (size_t)r0 * 128 + voff) = __floats2half2_rn(v00, v01);
            if (r1 < NN) *reinterpret_cast<__half2*>(d_kvh + (size_t)r1 * 128 + voff) = __floats2half2_rn(v10, v11);
        } else if (mat == 3) {
            if (r0 < NN) *reinterpret_cast<float2*>(d_sn + (size_t)r0 * HID + jj) = make_float2(v00, v01);
            if (r1 < NN) *reinterpret_cast<float2*>(d_sn + (size_t)r1 * HID + jj) = make_float2(v10, v11);
        } else {
            if (r0 < NN) *reinterpret_cast<float2*>(d_qwn + (size_t)r0 * HID + jj) = make_float2(v00, v01);
            if (r1 < NN) *reinterpret_cast<float2*>(d_qwn + (size_t)r1 * HID + jj) = make_float2(v10, v11);
        }
    }
}
#define QKVS_SMEM ((64 * HS_STRIDE + 64 * WS_STRIDE + 320) * 4)

// softmax body with EXPLICIT per-stream state (M, DEN, ACC, EAC)
#define ATTN_BODY(CKV, CE, CVLD, M, DEN, ACC, EAC) do {                           \
    float2 k01 = __half22float2(*reinterpret_cast<const __half2*>(&(CKV).x));     \
    float2 k23 = __half22float2(*reinterpret_cast<const __half2*>(&(CKV).y));     \
    float2 v01 = __half22float2(*reinterpret_cast<const __half2*>(&(CKV).z));     \
    float2 v23 = __half22float2(*reinterpret_cast<const __half2*>(&(CKV).w));     \
    float2 e01 = __half22float2(*reinterpret_cast<const __half2*>(&(CE).x));      \
    float2 e23 = __half22float2(*reinterpret_cast<const __half2*>(&(CE).y));      \
    float pp = q.x * k01.x + q.y * k01.y + q.z * k23.x + q.w * k23.y              \
             + qw.x * e01.x + qw.y * e01.y + qw.z * e23.x + qw.w * e23.y;         \
    pp += __shfl_xor_sync(0xffffffffu, pp, 1);                                    \
    pp += __shfl_xor_sync(0xffffffffu, pp, 2);                                    \
    pp = (CVLD) ? pp * 0.36067376022224085f : -1e30f;                             \
    float w;                                                                      \
    if ((CVLD) && pp > (M)) {                                                     \
        float sc = ex2((M) - pp);                                                 \
        (M) = pp;                                                                 \
        (DEN) *= sc;                                                              \
        (ACC).x *= sc; (ACC).y *= sc; (ACC).z *= sc; (ACC).w *= sc;               \
        (EAC).x *= sc; (EAC).y *= sc; (EAC).z *= sc; (EAC).w *= sc;               \
        w = 1.0f;                                                                 \
    } else {                                                                      \
        w = ex2(pp - (M));                                                        \
        w = (CVLD) ? w : 0.f;                                                     \
    }                                                                             \
    (DEN) += w;                                                                   \
    (ACC).x += w * v01.x; (ACC).y += w * v01.y; (ACC).z += w * v23.x; (ACC).w += w * v23.y; \
    (EAC).x += w * e01.x; (EAC).y += w * e01.y; (EAC).z += w * e23.x; (EAC).w += w * e23.y; \
} while (0)

// ---------------- fused attention: half-warp per edge, warp per node -------------
// lane = 16*hf + 4*head + p. KV as one uint4 (interleaved fp16); ea sequential
// fp16. TWO INDEPENDENT softmax streams per half (A=even it, B=odd it) so the
// scale/accumulate chains of consecutive iterations overlap; lane-local merge at
// the end, then the hf cross-half merge. Warp-uniform trip counts; invalid slots
// clamp loads and contribute w=0. Depth-2 prefetch per stream as before.
__global__ __launch_bounds__(256) void attn_kernel(const float* __restrict__ We,
                                                   int layer) {
    __shared__ float WeS[16 * 68 + 4];  // skewed: [r*68 + col + (col>>4)]
    int t = threadIdx.x;
    const float* Wel = We + layer * EDGE_IN * HID;
    for (int u = t; u < EDGE_IN * HID; u += 256) {
        int r = u >> 6, col = u & 63;
        WeS[r * 68 + col + (col >> 4)] = Wel[u];
    }
    __syncthreads();

    int lane = t & 31;
    int warp = t >> 5;
    int n = blockIdx.x * 8 + warp;
    if (n >= NN) return;

    int hf = lane >> 4;
    int hl = lane & 15;
    int h = hl >> 2;
    int p = hl & 3;
    int cbs = hl * 4 + h;

    float4 q  = reinterpret_cast<const float4*>(d_qn)[n * 16 + hl];
    float4 qw = reinterpret_cast<const float4*>(d_qwn)[n * 16 + hl];

    float mA = -1e30f, denA = 0.f;
    float4 accA = make_float4(0.f, 0.f, 0.f, 0.f);
    float4 eacA = make_float4(0.f, 0.f, 0.f, 0.f);
    float mB = -1e30f, denB = 0.f;
    float4 accB = make_float4(0.f, 0.f, 0.f, 0.f);
    float4 eacB = make_float4(0.f, 0.f, 0.f, 0.f);

    int beg = d_offs[n], end = d_offs[n + 1];
    int d = end - beg;
    int itmax = (d + 1) >> 1;          // warp-uniform trip count

    int iA = beg + hf;                 // even-iteration edge cursor
    int iB = beg + hf + 2;             // odd-iteration edge cursor
    uint4 kvA, kvB;
    uint2 eA, eB;
    bool vldA = false, vldB = false, vldA2 = false, vldB2 = false;
    int srcA2 = 0, posA2 = 0, srcB2 = 0, posB2 = 0;
    if (itmax > 0) {
        int c = end - 1;
        vldA = (iA < end);
        int posA = vldA ? iA : c;
        int srcA = d_ssrc[posA];
        kvA = *reinterpret_cast<const uint4*>(d_kvh + (size_t)srcA * 128 + hl * 8);
        eA  = *reinterpret_cast<const uint2*>(d_seah + (size_t)posA * 16 + p * 4);
        vldB = (iB < end);
        int posB = vldB ? iB : c;
        int srcB = d_ssrc[posB];
        kvB = *reinterpret_cast<const uint4*>(d_kvh + (size_t)srcB * 128 + hl * 8);
        eB  = *reinterpret_cast<const uint2*>(d_seah + (size_t)posB * 16 + p * 4);
        vldA2 = (iA + 4 < end);
        posA2 = vldA2 ? (iA + 4) : c;
        srcA2 = d_ssrc[posA2];
        vldB2 = (iB + 4 < end);
        posB2 = vldB2 ? (iB + 4) : c;
        srcB2 = d_ssrc[posB2];
    }
    for (int it = 0; it < itmax; it += 2) {
        // ---- even iteration (stream A) ----
        {
            uint4 ckv = kvA;
            uint2 ce = eA;
            bool cvld = vldA;
            if (it + 2 < itmax) {
                kvA = *reinterpret_cast<const uint4*>(d_kvh + (size_t)srcA2 * 128 + hl * 8);
                eA  = *reinterpret_cast<const uint2*>(d_seah + (size_t)posA2 * 16 + p * 4);
                vldA = vldA2;
                iA += 4;
                int i8 = iA + 4;
                vldA2 = (i8 < end);
                posA2 = vldA2 ? i8 : (end - 1);
                srcA2 = d_ssrc[posA2];
            }
            ATTN_BODY(ckv, ce, cvld, mA, denA, accA, eacA);
        }
        // ---- odd iteration (stream B) ----
        if (it + 1 < itmax) {
            uint4 ckv = kvB;
            uint2 ce = eB;
            bool cvld = vldB;
            if (it + 3 < itmax) {
                kvB = *reinterpret_cast<const uint4*>(d_kvh + (size_t)srcB2 * 128 + hl * 8);
                eB  = *reinterpret_cast<const uint2*>(d_seah + (size_t)posB2 * 16 + p * 4);
                vldB = vldB2;
                iB += 4;
                int i8 = iB + 4;
                vldB2 = (i8 < end);
                posB2 = vldB2 ? i8 : (end - 1);
                srcB2 = d_ssrc[posB2];
            }
            ATTN_BODY(ckv, ce, cvld, mB, denB, accB, eacB);
        }
    }

    // lane-local merge of streams A and B
    float m = fmaxf(mA, mB);
    float sclA = ex2(mA - m), sclB = ex2(mB - m);
    float den = denA * sclA + denB * sclB;
    float4 acc, eac;
    acc.x = accA.x * sclA + accB.x * sclB;
    acc.y = accA.y * sclA + accB.y * sclB;
    acc.z = accA.z * sclA + accB.z * sclB;
    acc.w = accA.w * sclA + accB.w * sclB;
    eac.x = eacA.x * sclA + eacB.x * sclB;
    eac.y = eacA.y * sclA + eacB.y * sclB;
    eac.z = eacA.z * sclA + eacB.z * sclB;
    eac.w = eacA.w * sclA + eacB.w * sclB;

    // fold edge-embedding: acc[c] += sum_r eacc[h][r] * We[r][c]   (conflict-free smem)
    float ea_arr[4] = {eac.x, eac.y, eac.z, eac.w};
    #pragma unroll
    for (int r = 0; r < 16; r++) {
        float ev = __shfl_sync(0xffffffffu, ea_arr[r & 3], (h << 2) + (r >> 2), 16);
        acc.x += ev * WeS[r * 68 + cbs + 0];
        acc.y += ev * WeS[r * 68 + cbs + 1];
        acc.z += ev * WeS[r * 68 + cbs + 2];
        acc.w += ev * WeS[r * 68 + cbs + 3];
    }

    // merge the two half-warp softmax streams
    float om  = __shfl_xor_sync(0xffffffffu, m,    16);
    float odn = __shfl_xor_sync(0xffffffffu, den,  16);
    float oax = __shfl_xor_sync(0xffffffffu, acc.x, 16);
    float oay = __shfl_xor_sync(0xffffffffu, acc.y, 16);
    float oaz = __shfl_xor_sync(0xffffffffu, acc.z, 16);
    float oaw = __shfl_xor_sync(0xffffffffu, acc.w, 16);
    float mm = fmaxf(m, om);
    float sA = ex2(m - mm), sB = ex2(om - mm);
    den = den * sA + odn * sB;
    float ox = acc.x * sA + oax * sB;
    float oy = acc.y * sA + oay * sB;
    float oz = acc.z * sA + oaz * sB;
    float ow = acc.w * sA + oaw * sB;

    if (hf == 0) {
        float inv = 1.f / (den + 1e-16f);
        float4 s4 = reinterpret_cast<const float4*>(d_sn)[n * 16 + hl];
        float4 hc = reinterpret_cast<const float4*>(d_h)[n * 16 + hl];
        hc.x += fmaxf(ox * inv + s4.x, 0.f);
        hc.y += fmaxf(oy * inv + s4.y, 0.f);
        hc.z += fmaxf(oz * inv + s4.z, 0.f);
        hc.w += fmaxf(ow * inv + s4.w, 0.f);
        reinterpret_cast<float4*>(d_h)[n * 16 + hl] = hc;
    }
}

// ---------------- fused mean pool (sorted batch) + readout MLP -------------------
__global__ __launch_bounds__(1024) void pool_mlp_kernel(const int* __restrict__ batch,
    const float* __restrict__ W1, const float* __restrict__ b1,
    const float* __restrict__ W2, const float* __restrict__ b2,
    float* __restrict__ out) {
    __shared__ float red[1024];
    __shared__ float sp[64];
    __shared__ int bnd[2];
    int g = blockIdx.x, t = threadIdx.x;
    if (t == 0) {
        int lo = 0, hi = NN;
        while (lo < hi) { int mid = (lo + hi) >> 1; if (batch[mid] < g) lo = mid + 1; else hi = mid; }
        bnd[0] = lo;
        int lo2 = lo, hi2 = NN;
        while (lo2 < hi2) { int mid = (lo2 + hi2) >> 1; if (batch[mid] < g + 1) lo2 = mid + 1; else hi2 = mid; }
        bnd[1] = lo2;
    }
    __syncthreads();
    int lo = bnd[0], hi = bnd[1];
    int ch = t & 63, rg = t >> 6;     // 16 row groups
    float a = 0.f;
    for (int nd = lo + rg; nd < hi; nd += 16) a += d_h[(size_t)nd * HID + ch];
    red[t] = a;
    __syncthreads();
    if (t < 64) {
        float s = 0.f;
        #pragma unroll
        for (int j = 0; j < 16; j++) s += red[t + 64 * j];
        sp[t] = s / fmaxf((float)(hi - lo), 1.0f);
    }
    __syncthreads();
    if (t < 32) {
        float accv = b1[t];
        #pragma unroll
        for (int k = 0; k < HID; k++) accv += sp[k] * W1[k * 32 + t];
        float v = fmaxf(accv, 0.f) * W2[t];
        #pragma unroll
        for (int o = 16; o; o >>= 1) v += __shfl_xor_sync(0xffffffffu, v, o);
        if (t == 0) out[g] = v + b2[0];
    }
}

// ---------------- launch ----------------
extern "C" void kernel_launch(void* const* d_in, const int* in_sizes, int n_in,
                              void* d_out, int out_size) {
    const float* x   = (const float*)d_in[0];
    const int*   ei  = (const int*)d_in[1];
    const float* ea  = (const float*)d_in[2];
    const int*   bat = (const int*)d_in[3];
    const float* Wn  = (const float*)d_in[4];
    const float* bn  = (const float*)d_in[5];
    const float* Wq  = (const float*)d_in[6];
    const float* bq  = (const float*)d_in[7];
    const float* Wk  = (const float*)d_in[8];
    const float* bk  = (const float*)d_in[9];
    const float* Wv  = (const float*)d_in[10];
    const float* bv  = (const float*)d_in[11];
    const float* We  = (const float*)d_in[12];
    const float* Ws  = (const float*)d_in[13];
    const float* bs  = (const float*)d_in[14];
    const float* W1  = (const float*)d_in[15];
    const float* b1  = (const float*)d_in[16];
    const float* W2  = (const float*)d_in[17];
    const float* b2  = (const float*)d_in[18];
    float* out = (float*)d_out;

    cudaFuncSetAttribute(qkvs_kernel, cudaFuncAttributeMaxDynamicSharedMemorySize, 108 * 1024);

    // Order chosen so qkvs(l0) sits at launch index 3 (the slot ncu captures).
    // qkvs(l0) depends only on node_in + prep_M; the edge sort runs after it and
    // completes before attn(l0).
    node_in_kernel<<<(NN + 3) / 4, 256>>>(x, Wn, bn);                       // 0
    prep_M_kernel<<<dim3(16, NLAYER), 256>>>(Wq, bq, We);                   // 1
    zero_deg_kernel<<<(NN + 255) / 256, 256>>>();                           // 2
    qkvs_kernel<<<(NN + 63) / 64, 256, QKVS_SMEM>>>(                        // 3
        Wq, bq, Wk, bk, Wv, bv, Ws, bs, 0);
    hist_kernel<<<(EE + 255) / 256, 256>>>(ei);                             // 4
    int nb = (NN + 1023) / 1024;
    scan1_kernel<<<nb, 1024>>>();                                           // 5
    scan3_kernel<<<(NN + 255) / 256, 256>>>(nb);                            // 6
    scatter_kernel<<<(EE + 255) / 256, 256>>>(ei, ea);                      // 7

    attn_kernel<<<(NN + 7) / 8, 256>>>(We, 0);                              // 8
    for (int l = 1; l < NLAYER; l++) {
        qkvs_kernel<<<(NN + 63) / 64, 256, QKVS_SMEM>>>(
            Wq, bq, Wk, bk, Wv, bv, Ws, bs, l);
        attn_kernel<<<(NN + 7) / 8, 256>>>(We, l);
    }

    // fused mean pool + MLP head (batch is sorted)
    pool_mlp_kernel<<<GG, 1024>>>(bat, W1, b1, W2, b2, out);
}

// round 13
// speedup vs baseline: 1.0894x; 1.0894x over previous
#include <cuda_runtime.h>
#include <cuda_fp16.h>
#include <math.h>

#define NN 50000
#define EE 1600000
#define GG 64
#define NODE_IN 32
#define HID 64
#define EDGE_IN 16
#define NLAYER 3

// ---------------- device scratch (static globals; no runtime alloc) ----------------
__device__ float d_h[NN * HID];
__device__ float d_qn[NN * HID];
__device__ __align__(16) __half d_kvh[NN * 128];   // interleaved K|V fp16: lane hl -> [K4|V4]
__device__ float d_sn[NN * HID];
__device__ float d_qwn[NN * HID];   // per-node q.We projection (4 heads x 16 r, packed)
__device__ int   d_deg[NN];
__device__ int   d_offs[NN + 1];
__device__ int   d_cursor[NN];
__device__ int   d_bsum[64];
__device__ int   d_ssrc[EE];        // src sorted by dst (4B loads in attn loop)
__device__ int   d_seid[EE];        // original eid sorted by dst (permute only)
__device__ __align__(16) __half d_seah[(size_t)EE * EDGE_IN];  // fp16 permuted edge_attr
__device__ float d_M[NLAYER * HID * HID];   // fused Wq x We matrices (all layers)
__device__ float d_bqw[NLAYER * HID];

__device__ __forceinline__ float ex2(float x) {
    float r;
    asm("ex2.approx.f32 %0, %1;" : "=f"(r) : "f"(x));
    return r;
}
__device__ __forceinline__ unsigned tf32of(float x) {
    unsigned r;
    asm("cvt.rna.tf32.f32 %0, %1;" : "=r"(r) : "f"(x));
    return r;
}

// ---------------- preprocessing: counting sort of edges by dst ----------------
__global__ void zero_deg_kernel() {
    int i = blockIdx.x * blockDim.x + threadIdx.x;
    if (i < NN) d_deg[i] = 0;
}

__global__ void hist_kernel(const int* __restrict__ ei) {
    int e = blockIdx.x * blockDim.x + threadIdx.x;
    if (e < EE) atomicAdd(&d_deg[ei[EE + e]], 1);
}

__global__ void scan1_kernel() {
    __shared__ int s[1024];
    int t = threadIdx.x;
    int i = blockIdx.x * 1024 + t;
    int v = (i < NN) ? d_deg[i] : 0;
    s[t] = v;
    __syncthreads();
    for (int o = 1; o < 1024; o <<= 1) {
        int x = (t >= o) ? s[t - o] : 0;
        __syncthreads();
        s[t] += x;
        __syncthreads();
    }
    if (i < NN) d_offs[i] = s[t] - v;
    if (t == 1023) d_bsum[blockIdx.x] = s[t];
}

// scan3 folds the cross-block prefix: each block loads the <=64 block sums into
// smem and sums below its own block id.
__global__ void scan3_kernel(int nb) {
    __shared__ int pref[64];
    int t = threadIdx.x;
    if (t < nb) pref[t] = d_bsum[t];
    __syncthreads();
    int i = blockIdx.x * 256 + t;
    if (i < NN) {
        int b = i >> 10;
        int add = 0;
        for (int j = 0; j < b; j++) add += pref[j];
        int v = d_offs[i] + add;
        d_offs[i] = v;
        d_cursor[i] = v;
    }
    if (i == 0) {
        int tot = 0;
        for (int j = 0; j < nb; j++) tot += pref[j];
        d_offs[NN] = tot;   // == EE
    }
}

__global__ void scatter_kernel(const int* __restrict__ ei) {
    int e = blockIdx.x * blockDim.x + threadIdx.x;
    if (e < EE) {
        int dstv = ei[EE + e];
        int pos = atomicAdd(&d_cursor[dstv], 1);
        d_ssrc[pos] = ei[e];
        d_seid[pos] = e;
    }
}

// permute edge_attr into sorted-edge order, fp16 (51MB, L2-resident across layers)
__global__ void permute_eah_kernel(const float* __restrict__ ea) {
    int t = blockIdx.x * blockDim.x + threadIdx.x;
    if (t < EE * 4) {
        int pos = t >> 2;
        int u = t & 3;
        int eid = d_seid[pos];
        float4 v = reinterpret_cast<const float4*>(ea)[(size_t)eid * 4 + u];
        __half2 h0 = __floats2half2_rn(v.x, v.y);
        __half2 h1 = __floats2half2_rn(v.z, v.w);
        __half2* dst = reinterpret_cast<__half2*>(d_seah + (size_t)pos * 16 + u * 4);
        dst[0] = h0;
        dst[1] = h1;
    }
}

// ---------------- input embedding: h = relu(x @ Wn + bn) ----------------
__global__ __launch_bounds__(256) void node_in_kernel(const float* __restrict__ x,
                                                      const float* __restrict__ Wn,
                                                      const float* __restrict__ bn) {
    __shared__ float Wns[NODE_IN * HID];
    __shared__ float bns[HID];
    __shared__ float xs[4][NODE_IN];
    int t = threadIdx.x;
    for (int u = t; u < NODE_IN * HID; u += 256) Wns[u] = Wn[u];
    if (t < HID) bns[t] = bn[t];
    int j = t & 63, y = t >> 6;
    int node = blockIdx.x * 4 + y;
    if (j < NODE_IN && node < NN) xs[y][j] = x[node * NODE_IN + j];
    __syncthreads();
    if (node < NN) {
        float a = bns[j];
        #pragma unroll
        for (int k = 0; k < NODE_IN; k++) a += xs[y][k] * Wns[k * HID + j];
        d_h[(size_t)node * HID + j] = fmaxf(a, 0.f);
    }
}

// ---------------- all layers: M = per-head (Wq x We), bqw = per-head (bq x We) ----
__global__ void prep_M_kernel(const float* __restrict__ Wq, const float* __restrict__ bq,
                              const float* __restrict__ We) {
    int layer = blockIdx.y;
    int idx = blockIdx.x * 256 + threadIdx.x;
    const float* Wql = Wq + layer * HID * HID;
    const float* Wel = We + layer * EDGE_IN * HID;
    if (idx < HID * HID) {
        int krow = idx >> 6, col = idx & 63;
        int h = col >> 4, r = col & 15;
        float s = 0.f;
        #pragma unroll
        for (int c = 0; c < 16; c++)
            s += Wql[krow * HID + h * 16 + c] * Wel[r * HID + h * 16 + c];
        d_M[layer * HID * HID + idx] = s;
    }
    if (idx < HID) {
        int h = idx >> 4, r = idx & 15;
        const float* bql = bq + layer * HID;
        float s = 0.f;
        #pragma unroll
        for (int c = 0; c < 16; c++)
            s += bql[h * 16 + c] * Wel[r * HID + h * 16 + c];
        d_bqw[layer * HID + idx] = s;
    }
}

// ---------------- fused Q/K/V/Skip/QW node GEMM — tf32 tensor cores --------------
// Block: 64 nodes x 320 cols, 8 warps tiled 2 (m) x 4 (n): warp = 32 rows x 80
// cols = 2 m-tiles x 10 n-tiles of m16n8k8. B fragments are shared across the 2
// m-tiles -> LDS per k-step drops 44 -> 28 vs the 4x2 tiling (ncu: L1tex 61%).
// Both smem tiles are PRE-CONVERTED to tf32 at store time (one cvt per element).
// Strides 68 (hs) / 328 (ws) keep fragment loads conflict-free:
//   A: banks (gid*4+tg)%32 all distinct;  B: banks (tg*8+gid)%32 all distinct.
#define HS_STRIDE 68
#define WS_STRIDE 328
__global__ __launch_bounds__(256) void qkvs_kernel(
    const float* __restrict__ Wq, const float* __restrict__ bq,
    const float* __restrict__ Wk, const float* __restrict__ bk,
    const float* __restrict__ Wv, const float* __restrict__ bv,
    const float* __restrict__ Ws, const float* __restrict__ bs, int layer) {
    extern __shared__ float sm[];
    float* hs  = sm;                               // 64 x 68 (tf32 bits)
    float* ws  = sm + 64 * HS_STRIDE;              // 64 x 328 (tf32 bits, 320 used)
    float* bss = sm + 64 * HS_STRIDE + 64 * WS_STRIDE;   // 320 bias values (fp32)
    const float* Wm[5] = {Wq + layer * HID * HID, Wk + layer * HID * HID,
                          Wv + layer * HID * HID, Ws + layer * HID * HID,
                          d_M + layer * HID * HID};
    const float* bm[5] = {bq + layer * HID, bk + layer * HID, bv + layer * HID,
                          bs + layer * HID, d_bqw + layer * HID};
    int t = threadIdx.x;
    int node0 = blockIdx.x * 64;

    // weights -> smem, pre-converted to tf32
    #pragma unroll
    for (int u = 0; u < 20; u++) {
        int mat = u >> 2;
        int e0 = ((u & 3) * 256 + t) * 4;
        int k = e0 >> 6, jj = e0 & 63;
        float4 w4 = *reinterpret_cast<const float4*>(Wm[mat] + k * HID + jj);
        w4.x = __uint_as_float(tf32of(w4.x));
        w4.y = __uint_as_float(tf32of(w4.y));
        w4.z = __uint_as_float(tf32of(w4.z));
        w4.w = __uint_as_float(tf32of(w4.w));
        *reinterpret_cast<float4*>(ws + k * WS_STRIDE + mat * 64 + jj) = w4;
    }
    // h tile -> smem, pre-converted to tf32
    #pragma unroll
    for (int u = 0; u < 4; u++) {
        int e0 = (u * 256 + t) * 4;
        int row = e0 >> 6, k = e0 & 63;
        int node = node0 + row;
        float4 h4 = make_float4(0.f, 0.f, 0.f, 0.f);
        if (node < NN) h4 = *reinterpret_cast<const float4*>(d_h + (size_t)node * HID + k);
        h4.x = __uint_as_float(tf32of(h4.x));
        h4.y = __uint_as_float(tf32of(h4.y));
        h4.z = __uint_as_float(tf32of(h4.z));
        h4.w = __uint_as_float(tf32of(h4.w));
        *reinterpret_cast<float4*>(hs + row * HS_STRIDE + k) = h4;
    }
    for (int u = t; u < 320; u += 256) bss[u] = bm[u >> 6][u & 63];
    __syncthreads();

    int warp = t >> 5;
    int lane = t & 31;
    int rb = warp >> 2;          // m block: rows rb*32 .. +31 (2 m-tiles)
    int cb = warp & 3;           // n block: cols cb*80 .. +79 (10 n-tiles)
    int gid = lane >> 2;         // 0..7
    int tg  = lane & 3;          // 0..3

    float c[2][10][4];
    #pragma unroll
    for (int mt = 0; mt < 2; mt++)
        #pragma unroll
        for (int nt = 0; nt < 10; nt++) {
            c[mt][nt][0] = 0.f; c[mt][nt][1] = 0.f;
            c[mt][nt][2] = 0.f; c[mt][nt][3] = 0.f;
        }

    #pragma unroll
    for (int ks = 0; ks < 8; ks++) {
        int k0 = ks * 8;
        unsigned a[2][4];
        #pragma unroll
        for (int mt = 0; mt < 2; mt++) {
            const float* hb = hs + (rb * 32 + mt * 16) * HS_STRIDE + k0;
            a[mt][0] = __float_as_uint(hb[gid * HS_STRIDE + tg]);
            a[mt][1] = __float_as_uint(hb[(gid + 8) * HS_STRIDE + tg]);
            a[mt][2] = __float_as_uint(hb[gid * HS_STRIDE + tg + 4]);
            a[mt][3] = __float_as_uint(hb[(gid + 8) * HS_STRIDE + tg + 4]);
        }
        #pragma unroll
        for (int nt = 0; nt < 10; nt++) {
            int coln = cb * 80 + nt * 8 + gid;
            unsigned b0 = __float_as_uint(ws[(k0 + tg) * WS_STRIDE + coln]);
            unsigned b1 = __float_as_uint(ws[(k0 + 4 + tg) * WS_STRIDE + coln]);
            #pragma unroll
            for (int mt = 0; mt < 2; mt++) {
                asm volatile(
                    "mma.sync.aligned.m16n8k8.row.col.f32.tf32.tf32.f32 "
                    "{%0,%1,%2,%3}, {%4,%5,%6,%7}, {%8,%9}, {%0,%1,%2,%3};"
                    : "+f"(c[mt][nt][0]), "+f"(c[mt][nt][1]),
                      "+f"(c[mt][nt][2]), "+f"(c[mt][nt][3])
                    : "r"(a[mt][0]), "r"(a[mt][1]), "r"(a[mt][2]), "r"(a[mt][3]),
                      "r"(b0), "r"(b1));
            }
        }
    }

    // epilogue: add bias, store. K/V go interleaved fp16 into d_kvh.
    #pragma unroll
    for (int mt = 0; mt < 2; mt++) {
        int r0 = node0 + rb * 32 + mt * 16 + gid;
        int r1 = r0 + 8;
        #pragma unroll
        for (int nt = 0; nt < 10; nt++) {
            int col = cb * 80 + nt * 8 + tg * 2;
            int mat = col >> 6, jj = col & 63;
            float b0 = bss[col], b1 = bss[col + 1];
            float v00 = c[mt][nt][0] + b0, v01 = c[mt][nt][1] + b1;   // row r0
            float v10 = c[mt][nt][2] + b0, v11 = c[mt][nt][3] + b1;   // row r1
            if (mat == 0) {
                if (r0 < NN) *reinterpret_cast<float2*>(d_qn + (size_t)r0 * HID + jj) = make_float2(v00, v01);
                if (r1 < NN) *reinterpret_cast<float2*>(d_qn + (size_t)r1 * HID + jj) = make_float2(v10, v11);
            } else if (mat == 1) {
                int koff = (jj >> 2) * 8 + (jj & 3);
                if (r0 < NN) *reinterpret_cast<__half2*>(d_kvh + (size_t)r0 * 128 + koff) = __floats2half2_rn(v00, v01);
                if (r1 < NN) *reinterpret_cast<__half2*>(d_kvh + (size_t)r1 * 128 + koff) = __floats2half2_rn(v10, v11);
            } else if (mat == 2) {
                int voff = (jj >> 2) * 8 + 4 + (jj & 3);
                if (r0 < NN) *reinterpret_cast<__half2*>(d_kvh + (size_t)r0 * 128 + voff) = __floats2half2_rn(v00, v01);
                if (r1 < NN) *reinterpret_cast<__half2*>(d_kvh + (size_t)r1 * 128 + voff) = __floats2half2_rn(v10, v11);
            } else if (mat == 3) {
                if (r0 < NN) *reinterpret_cast<float2*>(d_sn + (size_t)r0 * HID + jj) = make_float2(v00, v01);
                if (r1 < NN) *reinterpret_cast<float2*>(d_sn + (size_t)r1 * HID + jj) = make_float2(v10, v11);
            } else {
                if (r0 < NN) *reinterpret_cast<float2*>(d_qwn + (size_t)r0 * HID + jj) = make_float2(v00, v01);
                if (r1 < NN) *reinterpret_cast<float2*>(d_qwn + (size_t)r1 * HID + jj) = make_float2(v10, v11);
            }
        }
    }
}
#define QKVS_SMEM ((64 * HS_STRIDE + 64 * WS_STRIDE + 320) * 4)

// softmax body (R11 shared-state version; CKV = uint4 K4|V4 halves, CE = uint2)
#define ATTN_BODY(CKV, CE, CVLD) do {                                             \
    float2 k01 = __half22float2(*reinterpret_cast<const __half2*>(&(CKV).x));     \
    float2 k23 = __half22float2(*reinterpret_cast<const __half2*>(&(CKV).y));     \
    float2 v01 = __half22float2(*reinterpret_cast<const __half2*>(&(CKV).z));     \
    float2 v23 = __half22float2(*reinterpret_cast<const __half2*>(&(CKV).w));     \
    float2 e01 = __half22float2(*reinterpret_cast<const __half2*>(&(CE).x));      \
    float2 e23 = __half22float2(*reinterpret_cast<const __half2*>(&(CE).y));      \
    float pp = q.x * k01.x + q.y * k01.y + q.z * k23.x + q.w * k23.y              \
             + qw.x * e01.x + qw.y * e01.y + qw.z * e23.x + qw.w * e23.y;         \
    pp += __shfl_xor_sync(0xffffffffu, pp, 1);                                    \
    pp += __shfl_xor_sync(0xffffffffu, pp, 2);                                    \
    pp = (CVLD) ? pp * 0.36067376022224085f : -1e30f;                             \
    float w;                                                                      \
    if ((CVLD) && pp > m) {                                                       \
        float sc = ex2(m - pp);                                                   \
        m = pp;                                                                   \
        den *= sc;                                                                \
        acc.x *= sc; acc.y *= sc; acc.z *= sc; acc.w *= sc;                       \
        eac.x *= sc; eac.y *= sc; eac.z *= sc; eac.w *= sc;                       \
        w = 1.0f;                                                                 \
    } else {                                                                      \
        w = ex2(pp - m);                                                          \
        w = (CVLD) ? w : 0.f;                                                     \
    }                                                                             \
    den += w;                                                                     \
    acc.x += w * v01.x; acc.y += w * v01.y; acc.z += w * v23.x; acc.w += w * v23.y;\
    eac.x += w * e01.x; eac.y += w * e01.y; eac.z += w * e23.x; eac.w += w * e23.y;\
} while (0)

// ---------------- fused attention: half-warp per edge, warp per node -------------
// EXACT R11 structure (the 582us version): shared softmax state, depth-2 A/B
// prefetch buffers, warp-uniform trip count, clamped invalid slots with w=0.
__global__ __launch_bounds__(256) void attn_kernel(const float* __restrict__ We,
                                                   int layer) {
    __shared__ float WeS[16 * 68 + 4];  // skewed: [r*68 + col + (col>>4)]
    int t = threadIdx.x;
    const float* Wel = We + layer * EDGE_IN * HID;
    for (int u = t; u < EDGE_IN * HID; u += 256) {
        int r = u >> 6, col = u & 63;
        WeS[r * 68 + col + (col >> 4)] = Wel[u];
    }
    __syncthreads();

    int lane = t & 31;
    int warp = t >> 5;
    int n = blockIdx.x * 8 + warp;
    if (n >= NN) return;

    int hf = lane >> 4;
    int hl = lane & 15;
    int h = hl >> 2;
    int p = hl & 3;
    int cbs = hl * 4 + h;

    float4 q  = reinterpret_cast<const float4*>(d_qn)[n * 16 + hl];
    float4 qw = reinterpret_cast<const float4*>(d_qwn)[n * 16 + hl];

    float m = -1e30f, den = 0.f;
    float4 acc = make_float4(0.f, 0.f, 0.f, 0.f);
    float4 eac = make_float4(0.f, 0.f, 0.f, 0.f);

    int beg = d_offs[n], end = d_offs[n + 1];
    int d = end - beg;
    int itmax = (d + 1) >> 1;          // warp-uniform trip count

    int iA = beg + hf;                 // even-iteration edge cursor
    int iB = beg + hf + 2;             // odd-iteration edge cursor
    uint4 kvA, kvB;
    uint2 eA, eB;
    bool vldA = false, vldB = false, vldA2 = false, vldB2 = false;
    int srcA2 = 0, posA2 = 0, srcB2 = 0, posB2 = 0;
    if (itmax > 0) {
        int c = end - 1;
        vldA = (iA < end);
        int posA = vldA ? iA : c;
        int srcA = d_ssrc[posA];
        kvA = *reinterpret_cast<const uint4*>(d_kvh + (size_t)srcA * 128 + hl * 8);
        eA  = *reinterpret_cast<const uint2*>(d_seah + (size_t)posA * 16 + p * 4);
        vldB = (iB < end);
        int posB = vldB ? iB : c;
        int srcB = d_ssrc[posB];
        kvB = *reinterpret_cast<const uint4*>(d_kvh + (size_t)srcB * 128 + hl * 8);
        eB  = *reinterpret_cast<const uint2*>(d_seah + (size_t)posB * 16 + p * 4);
        vldA2 = (iA + 4 < end);
        posA2 = vldA2 ? (iA + 4) : c;
        srcA2 = d_ssrc[posA2];
        vldB2 = (iB + 4 < end);
        posB2 = vldB2 ? (iB + 4) : c;
        srcB2 = d_ssrc[posB2];
    }
    for (int it = 0; it < itmax; it += 2) {
        // ---- even iteration (buffer A) ----
        {
            uint4 ckv = kvA;
            uint2 ce = eA;
            bool cvld = vldA;
            if (it + 2 < itmax) {
                kvA = *reinterpret_cast<const uint4*>(d_kvh + (size_t)srcA2 * 128 + hl * 8);
                eA  = *reinterpret_cast<const uint2*>(d_seah + (size_t)posA2 * 16 + p * 4);
                vldA = vldA2;
                iA += 4;
                int i8 = iA + 4;
                vldA2 = (i8 < end);
                posA2 = vldA2 ? i8 : (end - 1);
                srcA2 = d_ssrc[posA2];
            }
            ATTN_BODY(ckv, ce, cvld);
        }
        // ---- odd iteration (buffer B) ----
        if (it + 1 < itmax) {
            uint4 ckv = kvB;
            uint2 ce = eB;
            bool cvld = vldB;
            if (it + 3 < itmax) {
                kvB = *reinterpret_cast<const uint4*>(d_kvh + (size_t)srcB2 * 128 + hl * 8);
                eB  = *reinterpret_cast<const uint2*>(d_seah + (size_t)posB2 * 16 + p * 4);
                vldB = vldB2;
                iB += 4;
                int i8 = iB + 4;
                vldB2 = (i8 < end);
                posB2 = vldB2 ? i8 : (end - 1);
                srcB2 = d_ssrc[posB2];
            }
            ATTN_BODY(ckv, ce, cvld);
        }
    }

    // fold edge-embedding: acc[c] += sum_r eacc[h][r] * We[r][c]   (conflict-free smem)
    float ea_arr[4] = {eac.x, eac.y, eac.z, eac.w};
    #pragma unroll
    for (int r = 0; r < 16; r++) {
        float ev = __shfl_sync(0xffffffffu, ea_arr[r & 3], (h << 2) + (r >> 2), 16);
        acc.x += ev * WeS[r * 68 + cbs + 0];
        acc.y += ev * WeS[r * 68 + cbs + 1];
        acc.z += ev * WeS[r * 68 + cbs + 2];
        acc.w += ev * WeS[r * 68 + cbs + 3];
    }

    // merge the two half-warp softmax streams
    float om  = __shfl_xor_sync(0xffffffffu, m,    16);
    float odn = __shfl_xor_sync(0xffffffffu, den,  16);
    float oax = __shfl_xor_sync(0xffffffffu, acc.x, 16);
    float oay = __shfl_xor_sync(0xffffffffu, acc.y, 16);
    float oaz = __shfl_xor_sync(0xffffffffu, acc.z, 16);
    float oaw = __shfl_xor_sync(0xffffffffu, acc.w, 16);
    float mm = fmaxf(m, om);
    float sA = ex2(m - mm), sB = ex2(om - mm);
    den = den * sA + odn * sB;
    float ox = acc.x * sA + oax * sB;
    float oy = acc.y * sA + oay * sB;
    float oz = acc.z * sA + oaz * sB;
    float ow = acc.w * sA + oaw * sB;

    if (hf == 0) {
        float inv = 1.f / (den + 1e-16f);
        float4 s4 = reinterpret_cast<const float4*>(d_sn)[n * 16 + hl];
        float4 hc = reinterpret_cast<const float4*>(d_h)[n * 16 + hl];
        hc.x += fmaxf(ox * inv + s4.x, 0.f);
        hc.y += fmaxf(oy * inv + s4.y, 0.f);
        hc.z += fmaxf(oz * inv + s4.z, 0.f);
        hc.w += fmaxf(ow * inv + s4.w, 0.f);
        reinterpret_cast<float4*>(d_h)[n * 16 + hl] = hc;
    }
}

// ---------------- fused mean pool (sorted batch) + readout MLP -------------------
__global__ __launch_bounds__(1024) void pool_mlp_kernel(const int* __restrict__ batch,
    const float* __restrict__ W1, const float* __restrict__ b1,
    const float* __restrict__ W2, const float* __restrict__ b2,
    float* __restrict__ out) {
    __shared__ float red[1024];
    __shared__ float sp[64];
    __shared__ int bnd[2];
    int g = blockIdx.x, t = threadIdx.x;
    if (t == 0) {
        int lo = 0, hi = NN;
        while (lo < hi) { int mid = (lo + hi) >> 1; if (batch[mid] < g) lo = mid + 1; else hi = mid; }
        bnd[0] = lo;
        int lo2 = lo, hi2 = NN;
        while (lo2 < hi2) { int mid = (lo2 + hi2) >> 1; if (batch[mid] < g + 1) lo2 = mid + 1; else hi2 = mid; }
        bnd[1] = lo2;
    }
    __syncthreads();
    int lo = bnd[0], hi = bnd[1];
    int ch = t & 63, rg = t >> 6;     // 16 row groups
    float a = 0.f;
    for (int nd = lo + rg; nd < hi; nd += 16) a += d_h[(size_t)nd * HID + ch];
    red[t] = a;
    __syncthreads();
    if (t < 64) {
        float s = 0.f;
        #pragma unroll
        for (int j = 0; j < 16; j++) s += red[t + 64 * j];
        sp[t] = s / fmaxf((float)(hi - lo), 1.0f);
    }
    __syncthreads();
    if (t < 32) {
        float accv = b1[t];
        #pragma unroll
        for (int k = 0; k < HID; k++) accv += sp[k] * W1[k * 32 + t];
        float v = fmaxf(accv, 0.f) * W2[t];
        #pragma unroll
        for (int o = 16; o; o >>= 1) v += __shfl_xor_sync(0xffffffffu, v, o);
        if (t == 0) out[g] = v + b2[0];
    }
}

// ---------------- launch ----------------
extern "C" void kernel_launch(void* const* d_in, const int* in_sizes, int n_in,
                              void* d_out, int out_size) {
    const float* x   = (const float*)d_in[0];
    const int*   ei  = (const int*)d_in[1];
    const float* ea  = (const float*)d_in[2];
    const int*   bat = (const int*)d_in[3];
    const float* Wn  = (const float*)d_in[4];
    const float* bn  = (const float*)d_in[5];
    const float* Wq  = (const float*)d_in[6];
    const float* bq  = (const float*)d_in[7];
    const float* Wk  = (const float*)d_in[8];
    const float* bk  = (const float*)d_in[9];
    const float* Wv  = (const float*)d_in[10];
    const float* bv  = (const float*)d_in[11];
    const float* We  = (const float*)d_in[12];
    const float* Ws  = (const float*)d_in[13];
    const float* bs  = (const float*)d_in[14];
    const float* W1  = (const float*)d_in[15];
    const float* b1  = (const float*)d_in[16];
    const float* W2  = (const float*)d_in[17];
    const float* b2  = (const float*)d_in[18];
    float* out = (float*)d_out;

    cudaFuncSetAttribute(qkvs_kernel, cudaFuncAttributeMaxDynamicSharedMemorySize, 108 * 1024);

    // qkvs(l0) kept at launch index 3 (ncu's capture slot) for profiling.
    node_in_kernel<<<(NN + 3) / 4, 256>>>(x, Wn, bn);                       // 0
    prep_M_kernel<<<dim3(16, NLAYER), 256>>>(Wq, bq, We);                   // 1
    zero_deg_kernel<<<(NN + 255) / 256, 256>>>();                           // 2
    qkvs_kernel<<<(NN + 63) / 64, 256, QKVS_SMEM>>>(                        // 3
        Wq, bq, Wk, bk, Wv, bv, Ws, bs, 0);
    hist_kernel<<<(EE + 255) / 256, 256>>>(ei);                             // 4
    int nb = (NN + 1023) / 1024;
    scan1_kernel<<<nb, 1024>>>();                                           // 5
    scan3_kernel<<<(NN + 255) / 256, 256>>>(nb);                            // 6
    scatter_kernel<<<(EE + 255) / 256, 256>>>(ei);                          // 7
    permute_eah_kernel<<<(EE * 4 + 255) / 256, 256>>>(ea);                  // 8

    attn_kernel<<<(NN + 7) / 8, 256>>>(We, 0);                              // 9
    for (int l = 1; l < NLAYER; l++) {
        qkvs_kernel<<<(NN + 63) / 64, 256, QKVS_SMEM>>>(
            Wq, bq, Wk, bk, Wv, bv, Ws, bs, l);
        attn_kernel<<<(NN + 7) / 8, 256>>>(We, l);
    }

    // fused mean pool + MLP head (batch is sorted)
    pool_mlp_kernel<<<GG, 1024>>>(bat, W1, b1, W2, b2, out);
}

// round 14
// speedup vs baseline: 1.1452x; 1.0513x over previous
#include <cuda_runtime.h>
#include <cuda_fp16.h>
#include <math.h>

#define NN 50000
#define EE 1600000
#define GG 64
#define NODE_IN 32
#define HID 64
#define EDGE_IN 16
#define NLAYER 3

// ---------------- device scratch (static globals; no runtime alloc) ----------------
__device__ float d_h[NN * HID];
__device__ float d_qn[NN * HID];
__device__ __align__(16) __half d_kvh[NN * 128];   // interleaved K|V fp16: lane hl -> [K4|V4]
__device__ float d_sn[NN * HID];
__device__ float d_qwn[NN * HID];   // per-node q.We projection (4 heads x 16 r, packed)
__device__ int   d_deg[NN];
__device__ int   d_offs[NN + 1];
__device__ int   d_cursor[NN];
__device__ int   d_bsum[64];
__device__ int   d_ssrc[EE];        // src sorted by dst (4B loads in attn loop)
__device__ __align__(16) __half d_seah[(size_t)EE * EDGE_IN];  // fp16 permuted edge_attr
__device__ float d_M[NLAYER * HID * HID];   // fused Wq x We matrices (all layers)
__device__ float d_bqw[NLAYER * HID];

__device__ __forceinline__ float ex2(float x) {
    float r;
    asm("ex2.approx.f32 %0, %1;" : "=f"(r) : "f"(x));
    return r;
}
__device__ __forceinline__ unsigned tf32of(float x) {
    unsigned r;
    asm("cvt.rna.tf32.f32 %0, %1;" : "=r"(r) : "f"(x));
    return r;
}

// ---------------- preprocessing: counting sort of edges by dst ----------------
__global__ void zero_deg_kernel() {
    int i = blockIdx.x * blockDim.x + threadIdx.x;
    if (i < NN) d_deg[i] = 0;
}

__global__ void hist_kernel(const int* __restrict__ ei) {
    int e = blockIdx.x * blockDim.x + threadIdx.x;
    if (e < EE) atomicAdd(&d_deg[ei[EE + e]], 1);
}

__global__ void scan1_kernel() {
    __shared__ int s[1024];
    int t = threadIdx.x;
    int i = blockIdx.x * 1024 + t;
    int v = (i < NN) ? d_deg[i] : 0;
    s[t] = v;
    __syncthreads();
    for (int o = 1; o < 1024; o <<= 1) {
        int x = (t >= o) ? s[t - o] : 0;
        __syncthreads();
        s[t] += x;
        __syncthreads();
    }
    if (i < NN) d_offs[i] = s[t] - v;
    if (t == 1023) d_bsum[blockIdx.x] = s[t];
}

// scan3 folds the cross-block prefix: each block loads the <=64 block sums into
// smem and sums below its own block id.
__global__ void scan3_kernel(int nb) {
    __shared__ int pref[64];
    int t = threadIdx.x;
    if (t < nb) pref[t] = d_bsum[t];
    __syncthreads();
    int i = blockIdx.x * 256 + t;
    if (i < NN) {
        int b = i >> 10;
        int add = 0;
        for (int j = 0; j < b; j++) add += pref[j];
        int v = d_offs[i] + add;
        d_offs[i] = v;
        d_cursor[i] = v;
    }
    if (i == 0) {
        int tot = 0;
        for (int j = 0; j < nb; j++) tot += pref[j];
        d_offs[NN] = tot;   // == EE
    }
}

// scatter + fp16 ea permute fused: ea[e] read is COALESCED (thread id == edge id);
// the converted 32B half-row goes to the sorted slot. Kills the permute kernel
// and the d_seid round-trip.
__global__ void scatter_kernel(const int* __restrict__ ei, const float* __restrict__ ea) {
    int e = blockIdx.x * blockDim.x + threadIdx.x;
    if (e < EE) {
        int dstv = ei[EE + e];
        int pos = atomicAdd(&d_cursor[dstv], 1);
        d_ssrc[pos] = ei[e];
        const float4* src = reinterpret_cast<const float4*>(ea) + (size_t)e * 4;
        float4 v0 = src[0], v1 = src[1], v2 = src[2], v3 = src[3];
        uint4 pk0, pk1;
        *reinterpret_cast<__half2*>(&pk0.x) = __floats2half2_rn(v0.x, v0.y);
        *reinterpret_cast<__half2*>(&pk0.y) = __floats2half2_rn(v0.z, v0.w);
        *reinterpret_cast<__half2*>(&pk0.z) = __floats2half2_rn(v1.x, v1.y);
        *reinterpret_cast<__half2*>(&pk0.w) = __floats2half2_rn(v1.z, v1.w);
        *reinterpret_cast<__half2*>(&pk1.x) = __floats2half2_rn(v2.x, v2.y);
        *reinterpret_cast<__half2*>(&pk1.y) = __floats2half2_rn(v2.z, v2.w);
        *reinterpret_cast<__half2*>(&pk1.z) = __floats2half2_rn(v3.x, v3.y);
        *reinterpret_cast<__half2*>(&pk1.w) = __floats2half2_rn(v3.z, v3.w);
        uint4* dst = reinterpret_cast<uint4*>(d_seah + (size_t)pos * 16);
        dst[0] = pk0;
        dst[1] = pk1;
    }
}

// ---------------- input embedding: h = relu(x @ Wn + bn) ----------------
__global__ __launch_bounds__(256) void node_in_kernel(const float* __restrict__ x,
                                                      const float* __restrict__ Wn,
                                                      const float* __restrict__ bn) {
    __shared__ float Wns[NODE_IN * HID];
    __shared__ float bns[HID];
    __shared__ float xs[4][NODE_IN];
    int t = threadIdx.x;
    for (int u = t; u < NODE_IN * HID; u += 256) Wns[u] = Wn[u];
    if (t < HID) bns[t] = bn[t];
    int j = t & 63, y = t >> 6;
    int node = blockIdx.x * 4 + y;
    if (j < NODE_IN && node < NN) xs[y][j] = x[node * NODE_IN + j];
    __syncthreads();
    if (node < NN) {
        float a = bns[j];
        #pragma unroll
        for (int k = 0; k < NODE_IN; k++) a += xs[y][k] * Wns[k * HID + j];
        d_h[(size_t)node * HID + j] = fmaxf(a, 0.f);
    }
}

// ---------------- all layers: M = per-head (Wq x We), bqw = per-head (bq x We) ----
__global__ void prep_M_kernel(const float* __restrict__ Wq, const float* __restrict__ bq,
                              const float* __restrict__ We) {
    int layer = blockIdx.y;
    int idx = blockIdx.x * 256 + threadIdx.x;
    const float* Wql = Wq + layer * HID * HID;
    const float* Wel = We + layer * EDGE_IN * HID;
    if (idx < HID * HID) {
        int krow = idx >> 6, col = idx & 63;
        int h = col >> 4, r = col & 15;
        float s = 0.f;
        #pragma unroll
        for (int c = 0; c < 16; c++)
            s += Wql[krow * HID + h * 16 + c] * Wel[r * HID + h * 16 + c];
        d_M[layer * HID * HID + idx] = s;
    }
    if (idx < HID) {
        int h = idx >> 4, r = idx & 15;
        const float* bql = bq + layer * HID;
        float s = 0.f;
        #pragma unroll
        for (int c = 0; c < 16; c++)
            s += bql[h * 16 + c] * Wel[r * HID + h * 16 + c];
        d_bqw[layer * HID + idx] = s;
    }
}

// ---------------- fused Q/K/V/Skip/QW node GEMM — tf32 tensor cores --------------
// 2 (m) x 4 (n) warp tiling; B frags shared across 2 m-tiles; smem pre-converted
// to tf32. Strides 68 / 328 conflict-free (verified R13, 32.5us).
#define HS_STRIDE 68
#define WS_STRIDE 328
__global__ __launch_bounds__(256) void qkvs_kernel(
    const float* __restrict__ Wq, const float* __restrict__ bq,
    const float* __restrict__ Wk, const float* __restrict__ bk,
    const float* __restrict__ Wv, const float* __restrict__ bv,
    const float* __restrict__ Ws, const float* __restrict__ bs, int layer) {
    extern __shared__ float sm[];
    float* hs  = sm;                               // 64 x 68 (tf32 bits)
    float* ws  = sm + 64 * HS_STRIDE;              // 64 x 328 (tf32 bits, 320 used)
    float* bss = sm + 64 * HS_STRIDE + 64 * WS_STRIDE;   // 320 bias values (fp32)
    const float* Wm[5] = {Wq + layer * HID * HID, Wk + layer * HID * HID,
                          Wv + layer * HID * HID, Ws + layer * HID * HID,
                          d_M + layer * HID * HID};
    const float* bm[5] = {bq + layer * HID, bk + layer * HID, bv + layer * HID,
                          bs + layer * HID, d_bqw + layer * HID};
    int t = threadIdx.x;
    int node0 = blockIdx.x * 64;

    #pragma unroll
    for (int u = 0; u < 20; u++) {
        int mat = u >> 2;
        int e0 = ((u & 3) * 256 + t) * 4;
        int k = e0 >> 6, jj = e0 & 63;
        float4 w4 = *reinterpret_cast<const float4*>(Wm[mat] + k * HID + jj);
        w4.x = __uint_as_float(tf32of(w4.x));
        w4.y = __uint_as_float(tf32of(w4.y));
        w4.z = __uint_as_float(tf32of(w4.z));
        w4.w = __uint_as_float(tf32of(w4.w));
        *reinterpret_cast<float4*>(ws + k * WS_STRIDE + mat * 64 + jj) = w4;
    }
    #pragma unroll
    for (int u = 0; u < 4; u++) {
        int e0 = (u * 256 + t) * 4;
        int row = e0 >> 6, k = e0 & 63;
        int node = node0 + row;
        float4 h4 = make_float4(0.f, 0.f, 0.f, 0.f);
        if (node < NN) h4 = *reinterpret_cast<const float4*>(d_h + (size_t)node * HID + k);
        h4.x = __uint_as_float(tf32of(h4.x));
        h4.y = __uint_as_float(tf32of(h4.y));
        h4.z = __uint_as_float(tf32of(h4.z));
        h4.w = __uint_as_float(tf32of(h4.w));
        *reinterpret_cast<float4*>(hs + row * HS_STRIDE + k) = h4;
    }
    for (int u = t; u < 320; u += 256) bss[u] = bm[u >> 6][u & 63];
    __syncthreads();

    int warp = t >> 5;
    int lane = t & 31;
    int rb = warp >> 2;          // m block: rows rb*32 .. +31 (2 m-tiles)
    int cb = warp & 3;           // n block: cols cb*80 .. +79 (10 n-tiles)
    int gid = lane >> 2;         // 0..7
    int tg  = lane & 3;          // 0..3

    float c[2][10][4];
    #pragma unroll
    for (int mt = 0; mt < 2; mt++)
        #pragma unroll
        for (int nt = 0; nt < 10; nt++) {
            c[mt][nt][0] = 0.f; c[mt][nt][1] = 0.f;
            c[mt][nt][2] = 0.f; c[mt][nt][3] = 0.f;
        }

    #pragma unroll
    for (int ks = 0; ks < 8; ks++) {
        int k0 = ks * 8;
        unsigned a[2][4];
        #pragma unroll
        for (int mt = 0; mt < 2; mt++) {
            const float* hb = hs + (rb * 32 + mt * 16) * HS_STRIDE + k0;
            a[mt][0] = __float_as_uint(hb[gid * HS_STRIDE + tg]);
            a[mt][1] = __float_as_uint(hb[(gid + 8) * HS_STRIDE + tg]);
            a[mt][2] = __float_as_uint(hb[gid * HS_STRIDE + tg + 4]);
            a[mt][3] = __float_as_uint(hb[(gid + 8) * HS_STRIDE + tg + 4]);
        }
        #pragma unroll
        for (int nt = 0; nt < 10; nt++) {
            int coln = cb * 80 + nt * 8 + gid;
            unsigned b0 = __float_as_uint(ws[(k0 + tg) * WS_STRIDE + coln]);
            unsigned b1 = __float_as_uint(ws[(k0 + 4 + tg) * WS_STRIDE + coln]);
            #pragma unroll
            for (int mt = 0; mt < 2; mt++) {
                asm volatile(
                    "mma.sync.aligned.m16n8k8.row.col.f32.tf32.tf32.f32 "
                    "{%0,%1,%2,%3}, {%4,%5,%6,%7}, {%8,%9}, {%0,%1,%2,%3};"
                    : "+f"(c[mt][nt][0]), "+f"(c[mt][nt][1]),
                      "+f"(c[mt][nt][2]), "+f"(c[mt][nt][3])
                    : "r"(a[mt][0]), "r"(a[mt][1]), "r"(a[mt][2]), "r"(a[mt][3]),
                      "r"(b0), "r"(b1));
            }
        }
    }

    #pragma unroll
    for (int mt = 0; mt < 2; mt++) {
        int r0 = node0 + rb * 32 + mt * 16 + gid;
        int r1 = r0 + 8;
        #pragma unroll
        for (int nt = 0; nt < 10; nt++) {
            int col = cb * 80 + nt * 8 + tg * 2;
            int mat = col >> 6, jj = col & 63;
            float b0 = bss[col], b1 = bss[col + 1];
            float v00 = c[mt][nt][0] + b0, v01 = c[mt][nt][1] + b1;   // row r0
            float v10 = c[mt][nt][2] + b0, v11 = c[mt][nt][3] + b1;   // row r1
            if (mat == 0) {
                if (r0 < NN) *reinterpret_cast<float2*>(d_qn + (size_t)r0 * HID + jj) = make_float2(v00, v01);
                if (r1 < NN) *reinterpret_cast<float2*>(d_qn + (size_t)r1 * HID + jj) = make_float2(v10, v11);
            } else if (mat == 1) {
                int koff = (jj >> 2) * 8 + (jj & 3);
                if (r0 < NN) *reinterpret_cast<__half2*>(d_kvh + (size_t)r0 * 128 + koff) = __floats2half2_rn(v00, v01);
                if (r1 < NN) *reinterpret_cast<__half2*>(d_kvh + (size_t)r1 * 128 + koff) = __floats2half2_rn(v10, v11);
            } else if (mat == 2) {
                int voff = (jj >> 2) * 8 + 4 + (jj & 3);
                if (r0 < NN) *reinterpret_cast<__half2*>(d_kvh + (size_t)r0 * 128 + voff) = __floats2half2_rn(v00, v01);
                if (r1 < NN) *reinterpret_cast<__half2*>(d_kvh + (size_t)r1 * 128 + voff) = __floats2half2_rn(v10, v11);
            } else if (mat == 3) {
                if (r0 < NN) *reinterpret_cast<float2*>(d_sn + (size_t)r0 * HID + jj) = make_float2(v00, v01);
                if (r1 < NN) *reinterpret_cast<float2*>(d_sn + (size_t)r1 * HID + jj) = make_float2(v10, v11);
            } else {
                if (r0 < NN) *reinterpret_cast<float2*>(d_qwn + (size_t)r0 * HID + jj) = make_float2(v00, v01);
                if (r1 < NN) *reinterpret_cast<float2*>(d_qwn + (size_t)r1 * HID + jj) = make_float2(v10, v11);
            }
        }
    }
}
#define QKVS_SMEM ((64 * HS_STRIDE + 64 * WS_STRIDE + 320) * 4)

// softmax body (R11/R13 shared-state version; CKV = uint4 K4|V4 halves, CE = uint2)
#define ATTN_BODY(CKV, CE, CVLD) do {                                             \
    float2 k01 = __half22float2(*reinterpret_cast<const __half2*>(&(CKV).x));     \
    float2 k23 = __half22float2(*reinterpret_cast<const __half2*>(&(CKV).y));     \
    float2 v01 = __half22float2(*reinterpret_cast<const __half2*>(&(CKV).z));     \
    float2 v23 = __half22float2(*reinterpret_cast<const __half2*>(&(CKV).w));     \
    float2 e01 = __half22float2(*reinterpret_cast<const __half2*>(&(CE).x));      \
    float2 e23 = __half22float2(*reinterpret_cast<const __half2*>(&(CE).y));      \
    float pp = q.x * k01.x + q.y * k01.y + q.z * k23.x + q.w * k23.y              \
             + qw.x * e01.x + qw.y * e01.y + qw.z * e23.x + qw.w * e23.y;         \
    pp += __shfl_xor_sync(0xffffffffu, pp, 1);                                    \
    pp += __shfl_xor_sync(0xffffffffu, pp, 2);                                    \
    pp = (CVLD) ? pp * 0.36067376022224085f : -1e30f;                             \
    float w;                                                                      \
    if ((CVLD) && pp > m) {                                                       \
        float sc = ex2(m - pp);                                                   \
        m = pp;                                                                   \
        den *= sc;                                                                \
        acc.x *= sc; acc.y *= sc; acc.z *= sc; acc.w *= sc;                       \
        eac.x *= sc; eac.y *= sc; eac.z *= sc; eac.w *= sc;                       \
        w = 1.0f;                                                                 \
    } else {                                                                      \
        w = ex2(pp - m);                                                          \
        w = (CVLD) ? w : 0.f;                                                     \
    }                                                                             \
    den += w;                                                                     \
    acc.x += w * v01.x; acc.y += w * v01.y; acc.z += w * v23.x; acc.w += w * v23.y;\
    eac.x += w * e01.x; eac.y += w * e01.y; eac.z += w * e23.x; eac.w += w * e23.y;\
} while (0)

// ---------------- fused attention: half-warp per edge, warp per node -------------
// EXACT R13 body/structure; block size 128 (4 warps) for finer CTA packing.
__global__ __launch_bounds__(128) void attn_kernel(const float* __restrict__ We,
                                                   int layer) {
    __shared__ float WeS[16 * 68 + 4];  // skewed: [r*68 + col + (col>>4)]
    int t = threadIdx.x;
    const float* Wel = We + layer * EDGE_IN * HID;
    for (int u = t; u < EDGE_IN * HID; u += 128) {
        int r = u >> 6, col = u & 63;
        WeS[r * 68 + col + (col >> 4)] = Wel[u];
    }
    __syncthreads();

    int lane = t & 31;
    int warp = t >> 5;
    int n = blockIdx.x * 4 + warp;
    if (n >= NN) return;

    int hf = lane >> 4;
    int hl = lane & 15;
    int h = hl >> 2;
    int p = hl & 3;
    int cbs = hl * 4 + h;

    float4 q  = reinterpret_cast<const float4*>(d_qn)[n * 16 + hl];
    float4 qw = reinterpret_cast<const float4*>(d_qwn)[n * 16 + hl];

    float m = -1e30f, den = 0.f;
    float4 acc = make_float4(0.f, 0.f, 0.f, 0.f);
    float4 eac = make_float4(0.f, 0.f, 0.f, 0.f);

    int beg = d_offs[n], end = d_offs[n + 1];
    int d = end - beg;
    int itmax = (d + 1) >> 1;          // warp-uniform trip count

    int iA = beg + hf;                 // even-iteration edge cursor
    int iB = beg + hf + 2;             // odd-iteration edge cursor
    uint4 kvA, kvB;
    uint2 eA, eB;
    bool vldA = false, vldB = false, vldA2 = false, vldB2 = false;
    int srcA2 = 0, posA2 = 0, srcB2 = 0, posB2 = 0;
    if (itmax > 0) {
        int c = end - 1;
        vldA = (iA < end);
        int posA = vldA ? iA : c;
        int srcA = d_ssrc[posA];
        kvA = *reinterpret_cast<const uint4*>(d_kvh + (size_t)srcA * 128 + hl * 8);
        eA  = *reinterpret_cast<const uint2*>(d_seah + (size_t)posA * 16 + p * 4);
        vldB = (iB < end);
        int posB = vldB ? iB : c;
        int srcB = d_ssrc[posB];
        kvB = *reinterpret_cast<const uint4*>(d_kvh + (size_t)srcB * 128 + hl * 8);
        eB  = *reinterpret_cast<const uint2*>(d_seah + (size_t)posB * 16 + p * 4);
        vldA2 = (iA + 4 < end);
        posA2 = vldA2 ? (iA + 4) : c;
        srcA2 = d_ssrc[posA2];
        vldB2 = (iB + 4 < end);
        posB2 = vldB2 ? (iB + 4) : c;
        srcB2 = d_ssrc[posB2];
    }
    for (int it = 0; it < itmax; it += 2) {
        // ---- even iteration (buffer A) ----
        {
            uint4 ckv = kvA;
            uint2 ce = eA;
            bool cvld = vldA;
            if (it + 2 < itmax) {
                kvA = *reinterpret_cast<const uint4*>(d_kvh + (size_t)srcA2 * 128 + hl * 8);
                eA  = *reinterpret_cast<const uint2*>(d_seah + (size_t)posA2 * 16 + p * 4);
                vldA = vldA2;
                iA += 4;
                int i8 = iA + 4;
                vldA2 = (i8 < end);
                posA2 = vldA2 ? i8 : (end - 1);
                srcA2 = d_ssrc[posA2];
            }
            ATTN_BODY(ckv, ce, cvld);
        }
        // ---- odd iteration (buffer B) ----
        if (it + 1 < itmax) {
            uint4 ckv = kvB;
            uint2 ce = eB;
            bool cvld = vldB;
            if (it + 3 < itmax) {
                kvB = *reinterpret_cast<const uint4*>(d_kvh + (size_t)srcB2 * 128 + hl * 8);
                eB  = *reinterpret_cast<const uint2*>(d_seah + (size_t)posB2 * 16 + p * 4);
                vldB = vldB2;
                iB += 4;
                int i8 = iB + 4;
                vldB2 = (i8 < end);
                posB2 = vldB2 ? i8 : (end - 1);
                srcB2 = d_ssrc[posB2];
            }
            ATTN_BODY(ckv, ce, cvld);
        }
    }

    // fold edge-embedding: acc[c] += sum_r eacc[h][r] * We[r][c]   (conflict-free smem)
    float ea_arr[4] = {eac.x, eac.y, eac.z, eac.w};
    #pragma unroll
    for (int r = 0; r < 16; r++) {
        float ev = __shfl_sync(0xffffffffu, ea_arr[r & 3], (h << 2) + (r >> 2), 16);
        acc.x += ev * WeS[r * 68 + cbs + 0];
        acc.y += ev * WeS[r * 68 + cbs + 1];
        acc.z += ev * WeS[r * 68 + cbs + 2];
        acc.w += ev * WeS[r * 68 + cbs + 3];
    }

    // merge the two half-warp softmax streams
    float om  = __shfl_xor_sync(0xffffffffu, m,    16);
    float odn = __shfl_xor_sync(0xffffffffu, den,  16);
    float oax = __shfl_xor_sync(0xffffffffu, acc.x, 16);
    float oay = __shfl_xor_sync(0xffffffffu, acc.y, 16);
    float oaz = __shfl_xor_sync(0xffffffffu, acc.z, 16);
    float oaw = __shfl_xor_sync(0xffffffffu, acc.w, 16);
    float mm = fmaxf(m, om);
    float sA = ex2(m - mm), sB = ex2(om - mm);
    den = den * sA + odn * sB;
    float ox = acc.x * sA + oax * sB;
    float oy = acc.y * sA + oay * sB;
    float oz = acc.z * sA + oaz * sB;
    float ow = acc.w * sA + oaw * sB;

    if (hf == 0) {
        float inv = 1.f / (den + 1e-16f);
        float4 s4 = reinterpret_cast<const float4*>(d_sn)[n * 16 + hl];
        float4 hc = reinterpret_cast<const float4*>(d_h)[n * 16 + hl];
        hc.x += fmaxf(ox * inv + s4.x, 0.f);
        hc.y += fmaxf(oy * inv + s4.y, 0.f);
        hc.z += fmaxf(oz * inv + s4.z, 0.f);
        hc.w += fmaxf(ow * inv + s4.w, 0.f);
        reinterpret_cast<float4*>(d_h)[n * 16 + hl] = hc;
    }
}

// ---------------- fused mean pool (sorted batch) + readout MLP -------------------
__global__ __launch_bounds__(1024) void pool_mlp_kernel(const int* __restrict__ batch,
    const float* __restrict__ W1, const float* __restrict__ b1,
    const float* __restrict__ W2, const float* __restrict__ b2,
    float* __restrict__ out) {
    __shared__ float red[1024];
    __shared__ float sp[64];
    __shared__ int bnd[2];
    int g = blockIdx.x, t = threadIdx.x;
    if (t == 0) {
        int lo = 0, hi = NN;
        while (lo < hi) { int mid = (lo + hi) >> 1; if (batch[mid] < g) lo = mid + 1; else hi = mid; }
        bnd[0] = lo;
        int lo2 = lo, hi2 = NN;
        while (lo2 < hi2) { int mid = (lo2 + hi2) >> 1; if (batch[mid] < g + 1) lo2 = mid + 1; else hi2 = mid; }
        bnd[1] = lo2;
    }
    __syncthreads();
    int lo = bnd[0], hi = bnd[1];
    int ch = t & 63, rg = t >> 6;     // 16 row groups
    float a = 0.f;
    for (int nd = lo + rg; nd < hi; nd += 16) a += d_h[(size_t)nd * HID + ch];
    red[t] = a;
    __syncthreads();
    if (t < 64) {
        float s = 0.f;
        #pragma unroll
        for (int j = 0; j < 16; j++) s += red[t + 64 * j];
        sp[t] = s / fmaxf((float)(hi - lo), 1.0f);
    }
    __syncthreads();
    if (t < 32) {
        float accv = b1[t];
        #pragma unroll
        for (int k = 0; k < HID; k++) accv += sp[k] * W1[k * 32 + t];
        float v = fmaxf(accv, 0.f) * W2[t];
        #pragma unroll
        for (int o = 16; o; o >>= 1) v += __shfl_xor_sync(0xffffffffu, v, o);
        if (t == 0) out[g] = v + b2[0];
    }
}

// ---------------- launch ----------------
extern "C" void kernel_launch(void* const* d_in, const int* in_sizes, int n_in,
                              void* d_out, int out_size) {
    const float* x   = (const float*)d_in[0];
    const int*   ei  = (const int*)d_in[1];
    const float* ea  = (const float*)d_in[2];
    const int*   bat = (const int*)d_in[3];
    const float* Wn  = (const float*)d_in[4];
    const float* bn  = (const float*)d_in[5];
    const float* Wq  = (const float*)d_in[6];
    const float* bq  = (const float*)d_in[7];
    const float* Wk  = (const float*)d_in[8];
    const float* bk  = (const float*)d_in[9];
    const float* Wv  = (const float*)d_in[10];
    const float* bv  = (const float*)d_in[11];
    const float* We  = (const float*)d_in[12];
    const float* Ws  = (const float*)d_in[13];
    const float* bs  = (const float*)d_in[14];
    const float* W1  = (const float*)d_in[15];
    const float* b1  = (const float*)d_in[16];
    const float* W2  = (const float*)d_in[17];
    const float* b2  = (const float*)d_in[18];
    float* out = (float*)d_out;

    cudaFuncSetAttribute(qkvs_kernel, cudaFuncAttributeMaxDynamicSharedMemorySize, 108 * 1024);

    // qkvs(l0) kept at launch index 3 (ncu's capture slot) for profiling.
    node_in_kernel<<<(NN + 3) / 4, 256>>>(x, Wn, bn);                       // 0
    prep_M_kernel<<<dim3(16, NLAYER), 256>>>(Wq, bq, We);                   // 1
    zero_deg_kernel<<<(NN + 255) / 256, 256>>>();                           // 2
    qkvs_kernel<<<(NN + 63) / 64, 256, QKVS_SMEM>>>(                        // 3
        Wq, bq, Wk, bk, Wv, bv, Ws, bs, 0);
    hist_kernel<<<(EE + 255) / 256, 256>>>(ei);                             // 4
    int nb = (NN + 1023) / 1024;
    scan1_kernel<<<nb, 1024>>>();                                           // 5
    scan3_kernel<<<(NN + 255) / 256, 256>>>(nb);                            // 6
    scatter_kernel<<<(EE + 255) / 256, 256>>>(ei, ea);                      // 7

    attn_kernel<<<(NN + 3) / 4, 128>>>(We, 0);                              // 8
    for (int l = 1; l < NLAYER; l++) {
        qkvs_kernel<<<(NN + 63) / 64, 256, QKVS_SMEM>>>(
            Wq, bq, Wk, bk, Wv, bv, Ws, bs, l);
        attn_kernel<<<(NN + 3) / 4, 128>>>(We, l);
    }

    // fused mean pool + MLP head (batch is sorted)
    pool_mlp_kernel<<<GG, 1024>>>(bat, W1, b1, W2, b2, out);
}